// round 16
// baseline (speedup 1.0000x reference)
#include <cuda_runtime.h>
#include <cuda_bf16.h>
#include <cstdint>

// Problem sizes (fixed by the reference)
#define NB 32
#define NL 1024
#define NC 64
#define NROWS (NB * NL)          // 32768
#define BN_EPS 1e-5f

// ---------------- scratch (device globals; no allocations allowed) ----------
__device__ float g_psum[256 * 64];
__device__ float g_psq[256 * 64];
__device__ float g_bp[64];                      // shift-folded bias
__device__ __nv_bfloat16 g_Wt_hi[64 * 64];      // (scale-folded W)^T hi [o][c]
__device__ __nv_bfloat16 g_Wt_lo[64 * 64];      // lo part
__device__ float g_sqd[NROWS];                  // sqrt(degree)
__device__ float g_rsd[NROWS];                  // rsqrt(degree)
__device__ float g_X[NROWS * 64];               // X = Hn @ W' + b' (fp32), 8 MB
__device__ __nv_bfloat16 g_Yt_hi[NB * 64 * NL]; // (rsd*X)^T per batch [b][n][l]
__device__ __nv_bfloat16 g_Yt_lo[NB * 64 * NL]; // lo part
__device__ __nv_bfloat16 g_Ahi[(size_t)NB * NL * NL];  // A bf16 hi, 64 MB
__device__ __nv_bfloat16 g_Alo[(size_t)NB * NL * NL];  // A bf16 lo, 64 MB

// ---------------- helpers ----------------------------------------------------
__device__ __forceinline__ void ldsm4(uint32_t* r, const __nv_bfloat16* p) {
    uint32_t a = (uint32_t)__cvta_generic_to_shared((const void*)p);
    asm volatile("ldmatrix.sync.aligned.m8n8.x4.shared.b16 {%0,%1,%2,%3}, [%4];"
                 : "=r"(r[0]), "=r"(r[1]), "=r"(r[2]), "=r"(r[3]) : "r"(a));
}
__device__ __forceinline__ void mma16816(float* c, const uint32_t* a,
                                         uint32_t b0, uint32_t b1) {
    asm volatile(
        "mma.sync.aligned.m16n8k16.row.col.f32.bf16.bf16.f32 "
        "{%0,%1,%2,%3}, {%4,%5,%6,%7}, {%8,%9}, {%0,%1,%2,%3};"
        : "+f"(c[0]), "+f"(c[1]), "+f"(c[2]), "+f"(c[3])
        : "r"(a[0]), "r"(a[1]), "r"(a[2]), "r"(a[3]), "r"(b0), "r"(b1));
}
// split x into bf16 hi/lo pairs, packed as bf16x2 words
__device__ __forceinline__ void split2(float x0, float x1,
                                       uint32_t& hi, uint32_t& lo) {
    __nv_bfloat162 h = __float22bfloat162_rn(make_float2(x0, x1));
    float2 hf = __bfloat1622float2(h);
    __nv_bfloat162 l = __float22bfloat162_rn(make_float2(x0 - hf.x, x1 - hf.y));
    hi = *(uint32_t*)&h;
    lo = *(uint32_t*)&l;
}
__device__ __forceinline__ void cpa16(uint32_t dst, const void* src) {
    asm volatile("cp.async.cg.shared.global [%0], [%1], 16;"
                 :: "r"(dst), "l"(src));
}

// ---------------- 1) BatchNorm statistics: partial sums ----------------------
__global__ void k_bn_partial(const float* __restrict__ H) {
    int t = threadIdx.x;
    int c = t & 63, rs = t >> 6;
    int row0 = blockIdx.x * 128;
    float s = 0.f, q = 0.f;
    const float* p = H + (size_t)(row0 + rs) * 64 + c;
    #pragma unroll 8
    for (int r = 0; r < 128; r += 4) {
        float v = p[(size_t)r * 64];
        s += v;
        q += v * v;
    }
    __shared__ float ss[256], sq[256];
    ss[t] = s; sq[t] = q;
    __syncthreads();
    if (t < 64) {
        s = ss[t] + ss[t + 64] + ss[t + 128] + ss[t + 192];
        q = sq[t] + sq[t + 64] + sq[t + 128] + sq[t + 192];
        g_psum[blockIdx.x * 64 + t] = s;
        g_psq[blockIdx.x * 64 + t] = q;
    }
}

// ---------------- 2) rowsum + A bf16 split; block 4096 does BN finalize ------
__global__ void k_rowsumF(const float* __restrict__ A,
                          const float* __restrict__ gamma,
                          const float* __restrict__ beta,
                          const float* __restrict__ W,
                          const float* __restrict__ bias) {
    if (blockIdx.x < 4096) {
        int warp = threadIdx.x >> 5, lane = threadIdx.x & 31;
        int row = blockIdx.x * 8 + warp;
        const float4* p = (const float4*)A + (size_t)row * 256;
        float s = 0.f;
        #pragma unroll
        for (int it = 0; it < 8; it++) {
            float4 v = p[it * 32 + lane];
            s += (v.x + v.y) + (v.z + v.w);
            uint2 uh, ul;
            split2(v.x, v.y, uh.x, ul.x);
            split2(v.z, v.w, uh.y, ul.y);
            size_t e = ((size_t)row << 10) + (it * 32 + lane) * 4;
            *(uint2*)(g_Ahi + e) = uh;
            *(uint2*)(g_Alo + e) = ul;
        }
        #pragma unroll
        for (int off = 16; off; off >>= 1)
            s += __shfl_xor_sync(0xffffffffu, s, off);
        if (lane == 0) {
            g_sqd[row] = sqrtf(s);
            g_rsd[row] = rsqrtf(s);
        }
    } else if (threadIdx.x < 64) {
        int c = threadIdx.x;
        float s = 0.f, q = 0.f;
        for (int i = 0; i < 256; i++) {
            s += g_psum[i * 64 + c];
            q += g_psq[i * 64 + c];
        }
        float mean = s * (1.0f / 32768.0f);
        float var  = q * (1.0f / 32768.0f) - mean * mean;
        float sc = gamma[c] * rsqrtf(var + BN_EPS);
        float sh = beta[c] - mean * sc;
        __shared__ float ssc[64], ssh[64];
        ssc[c] = sc; ssh[c] = sh;
        __syncwarp();
        __syncthreads();
        int o = c;
        float bp = bias[o];
        for (int cc = 0; cc < 64; cc++) {
            float w = W[cc * 64 + o];
            float wp = ssc[cc] * w;
            __nv_bfloat16 hi = __float2bfloat16_rn(wp);
            __nv_bfloat16 lo = __float2bfloat16_rn(wp - __bfloat162float(hi));
            g_Wt_hi[o * 64 + cc] = hi;
            g_Wt_lo[o * 64 + cc] = lo;
            bp += ssh[cc] * w;
        }
        g_bp[o] = bp;
    } else {
        __syncthreads();   // match barrier in finalize path
    }
}

// ---------------- 3) HMMA computeX: X = H@W'^T + b'; Yt = (rsd*X)^T ----------
#define WPAD 72
#define CX_HH 0
#define CX_HL (128 * WPAD)
#define CX_WH (2 * 128 * WPAD)
#define CX_WL (2 * 128 * WPAD + 64 * WPAD)
#define CX_SMEM ((2 * 128 * WPAD + 2 * 64 * WPAD) * 2)   // 55296 B
#define YS_STRIDE 132

__global__ void __launch_bounds__(256) k_computeX(const float* __restrict__ H) {
    extern __shared__ __align__(16) char sm[];
    __nv_bfloat16* Hh = (__nv_bfloat16*)sm + CX_HH;
    __nv_bfloat16* Hl = (__nv_bfloat16*)sm + CX_HL;
    __nv_bfloat16* Wh = (__nv_bfloat16*)sm + CX_WH;
    __nv_bfloat16* Wl = (__nv_bfloat16*)sm + CX_WL;
    float* ys = (float*)sm;                 // reused after MMA: [64][132] fp32
    __shared__ float rs[128];
    __shared__ float bpS[64];

    int t = threadIdx.x, wid = t >> 5, lane = t & 31;
    int r0 = blockIdx.x * 128;
    int wm = wid & 3, wn = wid >> 2;

    if (t < 128) rs[t] = g_rsd[r0 + t];
    if (t < 64)  bpS[t] = g_bp[t];

    const float4* H4 = (const float4*)(H + (size_t)r0 * 64);
    #pragma unroll
    for (int i = 0; i < 8; i++) {
        int idx = t + i * 256;
        int row = idx >> 4, c4 = idx & 15;
        float4 v = __ldg(&H4[idx]);
        uint2 uh, ul;
        split2(v.x, v.y, uh.x, ul.x);
        split2(v.z, v.w, uh.y, ul.y);
        *(uint2*)&Hh[row * WPAD + c4 * 4] = uh;
        *(uint2*)&Hl[row * WPAD + c4 * 4] = ul;
    }
    #pragma unroll
    for (int i = 0; i < 2; i++) {
        int idx = t + i * 256;
        int row = idx >> 3, c8 = idx & 7;
        *(uint4*)&Wh[row * WPAD + c8 * 8] = ((const uint4*)g_Wt_hi)[idx];
        *(uint4*)&Wl[row * WPAD + c8 * 8] = ((const uint4*)g_Wt_lo)[idx];
    }
    __syncthreads();

    float c[2][4][4];
    #pragma unroll
    for (int mi = 0; mi < 2; mi++)
        #pragma unroll
        for (int ni = 0; ni < 4; ni++)
            #pragma unroll
            for (int r = 0; r < 4; r++) c[mi][ni][r] = 0.f;

    int qr = (lane & 7) + ((lane & 8) ? 8 : 0);
    int qk = (lane & 16) ? 8 : 0;

    #pragma unroll
    for (int kk = 0; kk < 4; kk++) {
        int k0 = kk * 16 + qk;
        uint32_t ah[2][4], al[2][4], bh[2][4], bl[2][4];
        #pragma unroll
        for (int mi = 0; mi < 2; mi++) {
            int r = (wm * 32 + mi * 16 + qr) * WPAD + k0;
            ldsm4(ah[mi], Hh + r);
            ldsm4(al[mi], Hl + r);
        }
        #pragma unroll
        for (int nj = 0; nj < 2; nj++) {
            int r = (wn * 32 + nj * 16 + qr) * WPAD + k0;
            ldsm4(bh[nj], Wh + r);
            ldsm4(bl[nj], Wl + r);
        }
        #pragma unroll
        for (int mi = 0; mi < 2; mi++)
            #pragma unroll
            for (int ni = 0; ni < 4; ni++) {
                int g = ni >> 1, s = ni & 1;
                mma16816(c[mi][ni], ah[mi], bh[g][s], bh[g][s + 2]);
                mma16816(c[mi][ni], ah[mi], bl[g][s], bl[g][s + 2]);
                mma16816(c[mi][ni], al[mi], bh[g][s], bh[g][s + 2]);
            }
    }
    __syncthreads();   // tiles dead; smem becomes ys

    {
        int rbase = wm * 32 + (lane >> 2);
        int cbase = wn * 32 + (lane & 3) * 2;
        #pragma unroll
        for (int mi = 0; mi < 2; mi++)
            #pragma unroll
            for (int half = 0; half < 2; half++) {
                int rl = rbase + mi * 16 + half * 8;
                float rsv = rs[rl];
                #pragma unroll
                for (int ni = 0; ni < 4; ni++) {
                    int col = cbase + ni * 8;
                    float x0 = c[mi][ni][half * 2 + 0] + bpS[col];
                    float x1 = c[mi][ni][half * 2 + 1] + bpS[col + 1];
                    *(float2*)(g_X + (size_t)(r0 + rl) * 64 + col) =
                        make_float2(x0, x1);
                    ys[col * YS_STRIDE + rl]       = x0 * rsv;
                    ys[(col + 1) * YS_STRIDE + rl] = x1 * rsv;
                }
            }
    }
    __syncthreads();

    {
        int n = t >> 2, part = t & 3;
        int b = r0 >> 10, lb = r0 & 1023;
        #pragma unroll
        for (int g = 0; g < 4; g++) {
            int l = part * 32 + g * 8;
            const float* p = ys + n * YS_STRIDE + l;
            uint4 vh, vl;
            split2(p[0], p[1], vh.x, vl.x);
            split2(p[2], p[3], vh.y, vl.y);
            split2(p[4], p[5], vh.z, vl.z);
            split2(p[6], p[7], vh.w, vl.w);
            size_t dst = ((size_t)(b * 64 + n) << 10) + lb + l;
            *(uint4*)(g_Yt_hi + dst) = vh;
            *(uint4*)(g_Yt_lo + dst) = vl;
        }
    }
}

// ---------------- 4) cp.async HMMA GEMM + epilogue ---------------------------
// D[i,n] = sum_j A[i,j] * Y[j,n]   (bf16 hi/lo split, fp32 accum)
// out[i,n] = leaky( X[i,n] - sqd[i] * D[i,n] )
// All tiles pre-split bf16 in gmem -> pure cp.async 3-stage pipeline, no
// mainloop conversion, ~100 regs -> 2 CTA/SM spill-free, single wave.
#define APAD 40            // bf16 row stride (80B)
#define GA_STG  30720      // per-stage bytes: Ahi 10240 | Alo 10240 | Bhi 5120 | Blo 5120
#define GA_AHI  0
#define GA_ALO  10240
#define GA_BHI  20480
#define GA_BLO  25600
#define G_NSTAGE 3
#define G_SMEM  (G_NSTAGE * GA_STG)   // 92160
#define NCHUNK 32

__global__ void __launch_bounds__(256, 2) k_gemm_mma(float* __restrict__ out) {
    extern __shared__ __align__(16) char smg[];
    uint32_t sb = (uint32_t)__cvta_generic_to_shared(smg);

    int t = threadIdx.x, wid = t >> 5, lane = t & 31;
    int b = blockIdx.y, i0 = blockIdx.x * 128;
    int wm = wid & 3, wn = wid >> 2;

    // loader precompute: 6 x 16B chunks per thread per stage (1536 total)
    uint32_t dstoff[6];
    const __nv_bfloat16* srcp[6];
    #pragma unroll
    for (int s = 0; s < 6; s++) {
        int c = t + s * 256;
        int row, q;
        uint32_t area;
        const __nv_bfloat16* base;
        if (c < 512) {
            row = c >> 2; q = c & 3; area = GA_AHI;
            base = g_Ahi + ((size_t)(b * NL + i0 + row) << 10) + q * 8;
        } else if (c < 1024) {
            int cc = c - 512; row = cc >> 2; q = cc & 3; area = GA_ALO;
            base = g_Alo + ((size_t)(b * NL + i0 + row) << 10) + q * 8;
        } else if (c < 1280) {
            int cc = c - 1024; row = cc >> 2; q = cc & 3; area = GA_BHI;
            base = g_Yt_hi + ((size_t)(b * 64 + row) << 10) + q * 8;
        } else {
            int cc = c - 1280; row = cc >> 2; q = cc & 3; area = GA_BLO;
            base = g_Yt_lo + ((size_t)(b * 64 + row) << 10) + q * 8;
        }
        dstoff[s] = area + row * 80 + q * 16;
        srcp[s] = base;
    }

    auto ISSUE = [&](int ch, int stage) {
        uint32_t s0 = sb + stage * GA_STG;
        #pragma unroll
        for (int s = 0; s < 6; s++)
            cpa16(s0 + dstoff[s], (const char*)srcp[s] + ch * 64);
        asm volatile("cp.async.commit_group;" ::: "memory");
    };

    float c[2][4][4];
    #pragma unroll
    for (int mi = 0; mi < 2; mi++)
        #pragma unroll
        for (int ni = 0; ni < 4; ni++)
            #pragma unroll
            for (int r = 0; r < 4; r++) c[mi][ni][r] = 0.f;

    int qr = (lane & 7) + ((lane & 8) ? 8 : 0);
    int qk = (lane & 16) ? 8 : 0;

    ISSUE(0, 0);
    ISSUE(1, 1);
    int cur = 0;

    #pragma unroll 1
    for (int ch = 0; ch < NCHUNK; ch++) {
        if (ch + 2 < NCHUNK)
            asm volatile("cp.async.wait_group 1;" ::: "memory");
        else
            asm volatile("cp.async.wait_group 0;" ::: "memory");
        __syncthreads();

        const __nv_bfloat16* Ah = (const __nv_bfloat16*)(smg + cur * GA_STG + GA_AHI);
        const __nv_bfloat16* Al = (const __nv_bfloat16*)(smg + cur * GA_STG + GA_ALO);
        const __nv_bfloat16* Bh = (const __nv_bfloat16*)(smg + cur * GA_STG + GA_BHI);
        const __nv_bfloat16* Bl = (const __nv_bfloat16*)(smg + cur * GA_STG + GA_BLO);
        #pragma unroll
        for (int kk = 0; kk < 2; kk++) {
            int k0 = kk * 16 + qk;
            uint32_t ah[2][4], al[2][4], bh[2][4], bl[2][4];
            #pragma unroll
            for (int mi = 0; mi < 2; mi++) {
                int r = (wm * 32 + mi * 16 + qr) * APAD + k0;
                ldsm4(ah[mi], Ah + r);
                ldsm4(al[mi], Al + r);
            }
            #pragma unroll
            for (int nj = 0; nj < 2; nj++) {
                int r = (wn * 32 + nj * 16 + qr) * APAD + k0;
                ldsm4(bh[nj], Bh + r);
                ldsm4(bl[nj], Bl + r);
            }
            #pragma unroll
            for (int mi = 0; mi < 2; mi++)
                #pragma unroll
                for (int ni = 0; ni < 4; ni++) {
                    int g = ni >> 1, s = ni & 1;
                    mma16816(c[mi][ni], ah[mi], bh[g][s], bh[g][s + 2]);
                    mma16816(c[mi][ni], ah[mi], bl[g][s], bl[g][s + 2]);
                    mma16816(c[mi][ni], al[mi], bh[g][s], bh[g][s + 2]);
                }
        }
        if (ch + 2 < NCHUNK) {
            int nxt = cur + 2; if (nxt >= 3) nxt -= 3;
            ISSUE(ch + 2, nxt);
        }
        cur = (cur == 2) ? 0 : cur + 1;
    }

    // epilogue: out = leaky(X - sqd * D)
    float* outb = out + (size_t)b * NL * 64;
    const float* Xb = g_X + (size_t)b * NL * 64;
    const float* sqd_b = g_sqd + (size_t)b * NL;
    int r0 = i0 + wm * 32 + (lane >> 2);
    int cbase = wn * 32 + (lane & 3) * 2;
    #pragma unroll
    for (int mi = 0; mi < 2; mi++) {
        #pragma unroll
        for (int half = 0; half < 2; half++) {
            int row = r0 + mi * 16 + half * 8;
            float sq = __ldg(sqd_b + row);
            #pragma unroll
            for (int ni = 0; ni < 4; ni++) {
                int col = cbase + ni * 8;
                float2 x = *(const float2*)(Xb + (size_t)row * 64 + col);
                float v0 = x.x - sq * c[mi][ni][half * 2 + 0];
                float v1 = x.y - sq * c[mi][ni][half * 2 + 1];
                v0 = v0 > 0.f ? v0 : 0.01f * v0;
                v1 = v1 > 0.f ? v1 : 0.01f * v1;
                *(float2*)(outb + (size_t)row * 64 + col) = make_float2(v0, v1);
            }
        }
    }
}

// ---------------- launch -----------------------------------------------------
extern "C" void kernel_launch(void* const* d_in, const int* in_sizes, int n_in,
                              void* d_out, int out_size) {
    (void)in_sizes; (void)n_in; (void)out_size;
    const float* H     = (const float*)d_in[0];
    const float* A     = (const float*)d_in[1];
    const float* gamma = (const float*)d_in[2];
    const float* beta  = (const float*)d_in[3];
    const float* W     = (const float*)d_in[4];
    const float* bias  = (const float*)d_in[5];
    float* out = (float*)d_out;

    cudaFuncSetAttribute(k_gemm_mma, cudaFuncAttributeMaxDynamicSharedMemorySize,
                         G_SMEM);
    cudaFuncSetAttribute(k_computeX, cudaFuncAttributeMaxDynamicSharedMemorySize,
                         CX_SMEM);

    k_bn_partial<<<256, 256>>>(H);                       // idx 0
    k_rowsumF<<<4097, 256>>>(A, gamma, beta, W, bias);   // idx 1
    k_computeX<<<256, 256, CX_SMEM>>>(H);                // idx 2
    k_gemm_mma<<<dim3(8, NB), 256, G_SMEM>>>(out);       // idx 3 (profiled slot)
}